// round 1
// baseline (speedup 1.0000x reference)
#include <cuda_runtime.h>
#include <math.h>

#define NS 50000
#define NA 50000
#define ES 1000000
#define EA 500000
#define HD 64

// Scratch (allocation-free rule: __device__ globals), 16B-aligned for v4 atomics.
__device__ __align__(16) float g_sum_u[NS * HD];
__device__ __align__(16) float g_sum_x[NS * HD];
__device__ float g_deg[NS];

// Accurate-enough tanh: ~1e-7 rel err (MUFU ex2 + fast divide), cheap.
__device__ __forceinline__ float my_tanh(float v) {
    float ax = fabsf(v);
    float e  = __expf(-2.0f * ax);
    float t  = __fdividef(1.0f - e, 1.0f + e);
    return copysignf(t, v);
}

// acc[0..63] += v * w[0..63], weights via float4 broadcast loads from SMEM.
__device__ __forceinline__ void accum64(float* acc, const float* w, float v) {
#pragma unroll
    for (int j = 0; j < 64; j += 4) {
        float4 wv = *reinterpret_cast<const float4*>(w + j);
        acc[j + 0] += v * wv.x;
        acc[j + 1] += v * wv.y;
        acc[j + 2] += v * wv.z;
        acc[j + 3] += v * wv.w;
    }
}

__device__ __forceinline__ void red_add4(float* p, float a, float b, float c, float d) {
    asm volatile("red.global.add.v4.f32 [%0], {%1,%2,%3,%4};"
                 :: "l"(p), "f"(a), "f"(b), "f"(c), "f"(d) : "memory");
}

// Layers 2 and 3 (64->64 tanh, 64->64 linear). acc holds layer-1 preactivation on
// entry, final linear output on exit.
__device__ __forceinline__ void layers23(float* acc, const float* sW2, const float* sB2,
                                         const float* sW3, const float* sB3) {
    float z[64];
#pragma unroll
    for (int j = 0; j < 64; j++) z[j] = my_tanh(acc[j]);
#pragma unroll
    for (int j = 0; j < 64; j++) acc[j] = sB2[j];
#pragma unroll
    for (int k = 0; k < 64; k++) accum64(acc, sW2 + (k << 6), z[k]);
#pragma unroll
    for (int j = 0; j < 64; j++) z[j] = my_tanh(acc[j]);
#pragma unroll
    for (int j = 0; j < 64; j++) acc[j] = sB3[j];
#pragma unroll
    for (int k = 0; k < 64; k++) accum64(acc, sW3 + (k << 6), z[k]);
}

__device__ __forceinline__ void cp_smem(float* dst, const float* __restrict__ src,
                                        int n4, int tid, int nt) {
    const float4* s = reinterpret_cast<const float4*>(src);
    float4* d = reinterpret_cast<float4*>(dst);
    for (int i = tid; i < n4; i += nt) d[i] = s[i];
}

// ---------------------------------------------------------------------------
__global__ void zero_kernel(void) {
    int i = blockIdx.x * blockDim.x + threadIdx.x;
    if (i < NS * HD) { g_sum_u[i] = 0.0f; g_sum_x[i] = 0.0f; }
    if (i < NS) g_deg[i] = 0.0f;
}

// ---------------------------------------------------------------------------
// a2s edges: in = [pos_action[src](2), pos_state[dst](2), dis(1), u[src](8)] -> 13
__global__ void __launch_bounds__(128) a2s_kernel(
    const float* __restrict__ pos_state, const float* __restrict__ pos_action,
    const float* __restrict__ u,
    const int* __restrict__ esrc, const int* __restrict__ edst,
    const float* __restrict__ edis,
    const float* __restrict__ W1, const float* __restrict__ B1,
    const float* __restrict__ W2, const float* __restrict__ B2,
    const float* __restrict__ W3, const float* __restrict__ B3) {
    extern __shared__ float sm[];
    float* sW1 = sm;               // 13*64 = 832
    float* sB1 = sm + 832;         // 64
    float* sW2 = sm + 896;         // 4096
    float* sB2 = sm + 4992;        // 64
    float* sW3 = sm + 5056;        // 4096
    float* sB3 = sm + 9152;        // 64  -> total 9216 floats
    int tid = threadIdx.x, nt = blockDim.x;
    cp_smem(sW1, W1, 832 / 4, tid, nt);
    cp_smem(sB1, B1, 16, tid, nt);
    cp_smem(sW2, W2, 1024, tid, nt);
    cp_smem(sB2, B2, 16, tid, nt);
    cp_smem(sW3, W3, 1024, tid, nt);
    cp_smem(sB3, B3, 16, tid, nt);
    __syncthreads();

    int e = blockIdx.x * blockDim.x + threadIdx.x;
    if (e >= EA) return;
    int s = esrc[e], d = edst[e];

    float2 pa = *reinterpret_cast<const float2*>(pos_action + 2 * s);
    float2 ps = *reinterpret_cast<const float2*>(pos_state + 2 * d);
    float di = edis[e];

    float acc[64];
#pragma unroll
    for (int j = 0; j < 64; j++) acc[j] = sB1[j];
    accum64(acc, sW1 + 0 * 64, pa.x);
    accum64(acc, sW1 + 1 * 64, pa.y);
    accum64(acc, sW1 + 2 * 64, ps.x);
    accum64(acc, sW1 + 3 * 64, ps.y);
    accum64(acc, sW1 + 4 * 64, di);
    const float4* u4 = reinterpret_cast<const float4*>(u + 8 * (size_t)s);
#pragma unroll
    for (int i = 0; i < 2; i++) {
        float4 v = u4[i];
        accum64(acc, sW1 + (5 + 4 * i + 0) * 64, v.x);
        accum64(acc, sW1 + (5 + 4 * i + 1) * 64, v.y);
        accum64(acc, sW1 + (5 + 4 * i + 2) * 64, v.z);
        accum64(acc, sW1 + (5 + 4 * i + 3) * 64, v.w);
    }
    layers23(acc, sW2, sB2, sW3, sB3);

    float* outp = g_sum_u + (size_t)d * 64;
#pragma unroll
    for (int j = 0; j < 64; j += 4) red_add4(outp + j, acc[j], acc[j + 1], acc[j + 2], acc[j + 3]);
}

// ---------------------------------------------------------------------------
// s2s edges: in = [pos_state[src](2), pos_state[dst](2), dis(1), x[src](8), h[src](64)] -> 77
__global__ void __launch_bounds__(128) s2s_kernel(
    const float* __restrict__ pos_state, const float* __restrict__ xin,
    const float* __restrict__ h,
    const int* __restrict__ esrc, const int* __restrict__ edst,
    const float* __restrict__ edis,
    const float* __restrict__ W1, const float* __restrict__ B1,
    const float* __restrict__ W2, const float* __restrict__ B2,
    const float* __restrict__ W3, const float* __restrict__ B3) {
    extern __shared__ float sm[];
    float* sW1 = sm;                // 77*64 = 4928
    float* sB1 = sm + 4928;         // 64
    float* sW2 = sm + 4992;         // 4096
    float* sB2 = sm + 9088;         // 64
    float* sW3 = sm + 9152;         // 4096
    float* sB3 = sm + 13248;        // 64 -> total 13312 floats
    int tid = threadIdx.x, nt = blockDim.x;
    cp_smem(sW1, W1, 4928 / 4, tid, nt);
    cp_smem(sB1, B1, 16, tid, nt);
    cp_smem(sW2, W2, 1024, tid, nt);
    cp_smem(sB2, B2, 16, tid, nt);
    cp_smem(sW3, W3, 1024, tid, nt);
    cp_smem(sB3, B3, 16, tid, nt);
    __syncthreads();

    int e = blockIdx.x * blockDim.x + threadIdx.x;
    if (e >= ES) return;
    int s = esrc[e], d = edst[e];

    float2 ps = *reinterpret_cast<const float2*>(pos_state + 2 * s);
    float2 pd = *reinterpret_cast<const float2*>(pos_state + 2 * d);
    float di = edis[e];

    float acc[64];
#pragma unroll
    for (int j = 0; j < 64; j++) acc[j] = sB1[j];
    accum64(acc, sW1 + 0 * 64, ps.x);
    accum64(acc, sW1 + 1 * 64, ps.y);
    accum64(acc, sW1 + 2 * 64, pd.x);
    accum64(acc, sW1 + 3 * 64, pd.y);
    accum64(acc, sW1 + 4 * 64, di);
    const float4* x4 = reinterpret_cast<const float4*>(xin + 8 * (size_t)s);
#pragma unroll
    for (int i = 0; i < 2; i++) {
        float4 v = x4[i];
        accum64(acc, sW1 + (5 + 4 * i + 0) * 64, v.x);
        accum64(acc, sW1 + (5 + 4 * i + 1) * 64, v.y);
        accum64(acc, sW1 + (5 + 4 * i + 2) * 64, v.z);
        accum64(acc, sW1 + (5 + 4 * i + 3) * 64, v.w);
    }
    const float4* h4 = reinterpret_cast<const float4*>(h + 64 * (size_t)s);
#pragma unroll
    for (int i = 0; i < 16; i++) {
        float4 v = h4[i];
        accum64(acc, sW1 + (13 + 4 * i + 0) * 64, v.x);
        accum64(acc, sW1 + (13 + 4 * i + 1) * 64, v.y);
        accum64(acc, sW1 + (13 + 4 * i + 2) * 64, v.z);
        accum64(acc, sW1 + (13 + 4 * i + 3) * 64, v.w);
    }
    layers23(acc, sW2, sB2, sW3, sB3);

    float* outp = g_sum_x + (size_t)d * 64;
#pragma unroll
    for (int j = 0; j < 64; j += 4) red_add4(outp + j, acc[j], acc[j + 1], acc[j + 2], acc[j + 3]);
    atomicAdd(g_deg + d, 1.0f);
}

// ---------------------------------------------------------------------------
// node update: in = [pos_state(2), h(64), sum_u(64), mean_x(64), x(8)] -> 202
__global__ void __launch_bounds__(128) upd_kernel(
    const float* __restrict__ pos_state, const float* __restrict__ h,
    const float* __restrict__ xin,
    const float* __restrict__ W1, const float* __restrict__ B1,
    const float* __restrict__ W2, const float* __restrict__ B2,
    const float* __restrict__ W3, const float* __restrict__ B3,
    float* __restrict__ out) {
    extern __shared__ float sm[];
    float* sW1 = sm;                 // 202*64 = 12928
    float* sB1 = sm + 12928;         // 64
    float* sW2 = sm + 12992;         // 4096
    float* sB2 = sm + 17088;         // 64
    float* sW3 = sm + 17152;         // 4096
    float* sB3 = sm + 21248;         // 64 -> total 21312 floats
    int tid = threadIdx.x, nt = blockDim.x;
    cp_smem(sW1, W1, 12928 / 4, tid, nt);
    cp_smem(sB1, B1, 16, tid, nt);
    cp_smem(sW2, W2, 1024, tid, nt);
    cp_smem(sB2, B2, 16, tid, nt);
    cp_smem(sW3, W3, 1024, tid, nt);
    cp_smem(sB3, B3, 16, tid, nt);
    __syncthreads();

    int i = blockIdx.x * blockDim.x + threadIdx.x;
    if (i >= NS) return;

    float2 ps = *reinterpret_cast<const float2*>(pos_state + 2 * (size_t)i);
    float acc[64];
#pragma unroll
    for (int j = 0; j < 64; j++) acc[j] = sB1[j];
    accum64(acc, sW1 + 0 * 64, ps.x);
    accum64(acc, sW1 + 1 * 64, ps.y);
    const float4* h4 = reinterpret_cast<const float4*>(h + 64 * (size_t)i);
#pragma unroll
    for (int k = 0; k < 16; k++) {
        float4 v = h4[k];
        accum64(acc, sW1 + (2 + 4 * k + 0) * 64, v.x);
        accum64(acc, sW1 + (2 + 4 * k + 1) * 64, v.y);
        accum64(acc, sW1 + (2 + 4 * k + 2) * 64, v.z);
        accum64(acc, sW1 + (2 + 4 * k + 3) * 64, v.w);
    }
    const float4* su4 = reinterpret_cast<const float4*>(g_sum_u + 64 * (size_t)i);
#pragma unroll
    for (int k = 0; k < 16; k++) {
        float4 v = su4[k];
        accum64(acc, sW1 + (66 + 4 * k + 0) * 64, v.x);
        accum64(acc, sW1 + (66 + 4 * k + 1) * 64, v.y);
        accum64(acc, sW1 + (66 + 4 * k + 2) * 64, v.z);
        accum64(acc, sW1 + (66 + 4 * k + 3) * 64, v.w);
    }
    float dg = g_deg[i];
    float inv = __fdividef(1.0f, fmaxf(dg, 1.0f));
    const float4* sx4 = reinterpret_cast<const float4*>(g_sum_x + 64 * (size_t)i);
#pragma unroll
    for (int k = 0; k < 16; k++) {
        float4 v = sx4[k];
        accum64(acc, sW1 + (130 + 4 * k + 0) * 64, v.x * inv);
        accum64(acc, sW1 + (130 + 4 * k + 1) * 64, v.y * inv);
        accum64(acc, sW1 + (130 + 4 * k + 2) * 64, v.z * inv);
        accum64(acc, sW1 + (130 + 4 * k + 3) * 64, v.w * inv);
    }
    const float4* x4 = reinterpret_cast<const float4*>(xin + 8 * (size_t)i);
#pragma unroll
    for (int k = 0; k < 2; k++) {
        float4 v = x4[k];
        accum64(acc, sW1 + (194 + 4 * k + 0) * 64, v.x);
        accum64(acc, sW1 + (194 + 4 * k + 1) * 64, v.y);
        accum64(acc, sW1 + (194 + 4 * k + 2) * 64, v.z);
        accum64(acc, sW1 + (194 + 4 * k + 3) * 64, v.w);
    }
    layers23(acc, sW2, sB2, sW3, sB3);

    float4* o4 = reinterpret_cast<float4*>(out + 64 * (size_t)i);
#pragma unroll
    for (int j = 0; j < 16; j++)
        o4[j] = make_float4(acc[4 * j], acc[4 * j + 1], acc[4 * j + 2], acc[4 * j + 3]);
}

// ---------------------------------------------------------------------------
extern "C" void kernel_launch(void* const* d_in, const int* in_sizes, int n_in,
                              void* d_out, int out_size) {
    const float* pos_state  = (const float*)d_in[0];
    const float* pos_action = (const float*)d_in[1];
    const float* h          = (const float*)d_in[2];
    const float* x          = (const float*)d_in[3];
    const float* u          = (const float*)d_in[4];
    const int*   a2s_src    = (const int*)d_in[5];
    const int*   a2s_dst    = (const int*)d_in[6];
    const float* a2s_dis    = (const float*)d_in[7];
    const int*   s2s_src    = (const int*)d_in[8];
    const int*   s2s_dst    = (const int*)d_in[9];
    const float* s2s_dis    = (const float*)d_in[10];
    const float* u2h_w1 = (const float*)d_in[11];
    const float* u2h_b1 = (const float*)d_in[12];
    const float* u2h_w2 = (const float*)d_in[13];
    const float* u2h_b2 = (const float*)d_in[14];
    const float* u2h_w3 = (const float*)d_in[15];
    const float* u2h_b3 = (const float*)d_in[16];
    const float* x2h_w1 = (const float*)d_in[17];
    const float* x2h_b1 = (const float*)d_in[18];
    const float* x2h_w2 = (const float*)d_in[19];
    const float* x2h_b2 = (const float*)d_in[20];
    const float* x2h_w3 = (const float*)d_in[21];
    const float* x2h_b3 = (const float*)d_in[22];
    const float* upd_w1 = (const float*)d_in[23];
    const float* upd_b1 = (const float*)d_in[24];
    const float* upd_w2 = (const float*)d_in[25];
    const float* upd_b2 = (const float*)d_in[26];
    const float* upd_w3 = (const float*)d_in[27];
    const float* upd_b3 = (const float*)d_in[28];
    float* out = (float*)d_out;

    const int A2S_SMEM = 9216 * 4;
    const int S2S_SMEM = 13312 * 4;
    const int UPD_SMEM = 21312 * 4;
    cudaFuncSetAttribute(a2s_kernel, cudaFuncAttributeMaxDynamicSharedMemorySize, A2S_SMEM);
    cudaFuncSetAttribute(s2s_kernel, cudaFuncAttributeMaxDynamicSharedMemorySize, S2S_SMEM);
    cudaFuncSetAttribute(upd_kernel, cudaFuncAttributeMaxDynamicSharedMemorySize, UPD_SMEM);

    zero_kernel<<<(NS * HD + 255) / 256, 256>>>();

    a2s_kernel<<<(EA + 127) / 128, 128, A2S_SMEM>>>(
        pos_state, pos_action, u, a2s_src, a2s_dst, a2s_dis,
        u2h_w1, u2h_b1, u2h_w2, u2h_b2, u2h_w3, u2h_b3);

    s2s_kernel<<<(ES + 127) / 128, 128, S2S_SMEM>>>(
        pos_state, x, h, s2s_src, s2s_dst, s2s_dis,
        x2h_w1, x2h_b1, x2h_w2, x2h_b2, x2h_w3, x2h_b3);

    upd_kernel<<<(NS + 127) / 128, 128, UPD_SMEM>>>(
        pos_state, h, x,
        upd_w1, upd_b1, upd_w2, upd_b2, upd_w3, upd_b3,
        out);
}